// round 13
// baseline (speedup 1.0000x reference)
#include <cuda_runtime.h>
#include <cstdint>

#define NN      100000
#define EE      1600000
#define DD      128
#define NCAT    768
#define NLAYERS 4

// ---------------- scratch (static device globals; no runtime allocation) ----
__device__ float g_Wcat[NLAYERS * DD * NCAT];          // packed weights
__device__ float g_Y[(size_t)NN * 384];                // staging: beta_s|gamma_s|xs
__device__ float g_gamma[(size_t)NN * DD];
__device__ float g_beta[(size_t)NN * DD];
__device__ float g_h[(size_t)NN * DD];
__device__ float g_xb0[(size_t)NN * DD];
__device__ float g_xb1[(size_t)NN * DD];
__device__ int   g_counts[NN];
__device__ int   g_base[NN + 1];
__device__ int   g_cursor[NN];
__device__ int   g_srcs[EE + 8];    // +8 pad: safe 4-wide index prefetch at tail
__device__ float g_deginv[NN];
__device__ int   g_is64;            // edge_index dtype flag (1 = int64, 0 = int32)

// ---------------- dtype detection -------------------------------------------
// JAX demotes int64->int32 unless x64 is enabled; probe the buffer.
// If data is int32, an int64 read pairs two random indices -> hi word nonzero
// -> value >= NN with overwhelming probability across 256 probes.
__global__ void detect_kernel(const void* __restrict__ eidx, int* __restrict__ is64) {
    const long long* p64 = (const long long*)eidx;
    int ok = 1;
    for (int i = 0; i < 256; i++) {
        long long v = p64[i];
        if (v < 0 || v >= NN) { ok = 0; break; }
    }
    *is64 = ok;
}

__device__ __forceinline__ int edge_at(const void* eidx, int is64, long long pos) {
    return is64 ? (int)((const long long*)eidx)[pos]
                : ((const int*)eidx)[pos];
}

// ---------------- pack weights: Wcat[l][k][c] -------------------------------
// cols 0..127   = beta_s   (W_fskip[:, :128])
// cols 128..255 = gamma_s  (W_fskip[:, 128:])
// cols 256..383 = W_skip
// cols 384..511 = beta     (W_film[:, :128])
// cols 512..639 = gamma    (W_film[:, 128:])
// cols 640..767 = W_lin
__global__ void pack_weights_kernel(const float* __restrict__ W_lin,
                                    const float* __restrict__ W_film,
                                    const float* __restrict__ W_skip,
                                    const float* __restrict__ W_fskip,
                                    float* __restrict__ Wcat) {
    int idx = blockIdx.x * blockDim.x + threadIdx.x;
    if (idx >= NLAYERS * DD * NCAT) return;
    int l = idx / (DD * NCAT);
    int rem = idx % (DD * NCAT);
    int k = rem / NCAT;
    int c = rem % NCAT;
    float v;
    if (c < 256)      v = W_fskip[(size_t)l * DD * 256 + (size_t)k * 256 + c];
    else if (c < 384) v = W_skip [(size_t)l * DD * DD  + (size_t)k * DD  + (c - 256)];
    else if (c < 640) v = W_film [(size_t)l * DD * 256 + (size_t)k * 256 + (c - 384)];
    else              v = W_lin  [(size_t)l * DD * DD  + (size_t)k * DD  + (c - 640)];
    Wcat[idx] = v;
}

// ---------------- CSR build --------------------------------------------------
__global__ void zero_int_kernel(int* __restrict__ p, int n) {
    int i = blockIdx.x * blockDim.x + threadIdx.x;
    if (i < n) p[i] = 0;
}

__global__ void count_kernel(const void* __restrict__ eidx,
                             const int* __restrict__ is64,
                             int* __restrict__ counts) {
    int e = blockIdx.x * blockDim.x + threadIdx.x;
    if (e < EE) {
        int d = edge_at(eidx, *is64, (long long)EE + e);   // dst[e]
        atomicAdd(&counts[d], 1);
    }
}

// Single-block exclusive scan over counts -> base; also deg_inv and cursor init.
__global__ __launch_bounds__(1024) void scan_kernel(const int* __restrict__ counts,
                                                    int* __restrict__ base,
                                                    int* __restrict__ cursor,
                                                    float* __restrict__ deginv) {
    __shared__ int warp_pref[32];
    __shared__ int chunk_tot;
    __shared__ int carry_sh;
    int tid  = threadIdx.x;
    int lane = tid & 31;
    int wid  = tid >> 5;
    if (tid == 0) carry_sh = 0;
    __syncthreads();

    for (int start = 0; start < NN; start += 1024) {
        int i = start + tid;
        int v = (i < NN) ? counts[i] : 0;

        int incl = v;
#pragma unroll
        for (int off = 1; off < 32; off <<= 1) {
            int t = __shfl_up_sync(0xffffffffu, incl, off);
            if (lane >= off) incl += t;
        }
        if (lane == 31) warp_pref[wid] = incl;
        __syncthreads();

        if (wid == 0) {
            int wv = warp_pref[lane];
            int wincl = wv;
#pragma unroll
            for (int off = 1; off < 32; off <<= 1) {
                int t = __shfl_up_sync(0xffffffffu, wincl, off);
                if (lane >= off) wincl += t;
            }
            warp_pref[lane] = wincl - wv;
            if (lane == 31) chunk_tot = wincl;
        }
        __syncthreads();

        int c = carry_sh;
        if (i < NN) {
            int excl = c + warp_pref[wid] + incl - v;
            base[i]   = excl;
            cursor[i] = excl;
            deginv[i] = 1.0f / fmaxf((float)v, 1.0f);
        }
        __syncthreads();
        if (tid == 0) carry_sh = c + chunk_tot;
        __syncthreads();
    }
    if (tid == 0) base[NN] = carry_sh;
}

__global__ void scatter_kernel(const void* __restrict__ eidx,
                               const int* __restrict__ is64,
                               int* __restrict__ cursor,
                               int* __restrict__ srcs) {
    int e = blockIdx.x * blockDim.x + threadIdx.x;
    if (e < EE) {
        int f = *is64;
        int d = edge_at(eidx, f, (long long)EE + e);   // dst[e]
        int s = edge_at(eidx, f, (long long)e);        // src[e]
        int pos = atomicAdd(&cursor[d], 1);
        srcs[pos] = s;
    }
}

// ---------------- SGEMM with segment-routed epilogue ------------------------
// 128x128 tile, BK=16, 256 threads, 8x8 per thread, double-buffered smem.
// blockIdx.x selects the column tile (= segment):
//   0..2 -> staging Y384 (beta_s | gamma_s | xs)
//   3    -> beta  buffer (+ bf[j])
//   4    -> gamma buffer (+ bf[128+j])
//   5    -> h buffer
__global__ __launch_bounds__(256) void sgemm_kernel(const float* __restrict__ A,
                                                    const float* __restrict__ B,
                                                    const float* __restrict__ bf,
                                                    float* __restrict__ Y384,
                                                    float* __restrict__ beta,
                                                    float* __restrict__ gamma,
                                                    float* __restrict__ h,
                                                    int M) {
    const int BK = 16;
    __shared__ float As[2][BK][128];
    __shared__ float Bs[2][BK][128];

    int tid  = threadIdx.x;
    int bx   = blockIdx.x;
    int row0 = blockIdx.y * 128;
    int col0 = bx * 128;

    int arow = tid >> 1;            // 0..127
    int acol = (tid & 1) * 8;       // 0 or 8
    int brow = tid >> 4;            // 0..15
    int bcol = (tid & 15) * 8;      // 0..120

    int tr = (tid >> 4) * 8;
    int tc = (tid & 15) * 8;

    bool arow_ok = (row0 + arow < M);
    const float* Aptr = A + (size_t)(row0 + arow) * DD + acol;
    const float* Bptr = B + (size_t)brow * NCAT + col0 + bcol;

    float acc[8][8];
#pragma unroll
    for (int i = 0; i < 8; i++)
#pragma unroll
        for (int j = 0; j < 8; j++) acc[i][j] = 0.0f;

    // preload tile 0
    {
        float4 a0 = make_float4(0.f, 0.f, 0.f, 0.f);
        float4 a1 = make_float4(0.f, 0.f, 0.f, 0.f);
        if (arow_ok) {
            a0 = *(const float4*)(Aptr);
            a1 = *(const float4*)(Aptr + 4);
        }
        As[0][acol + 0][arow] = a0.x;
        As[0][acol + 1][arow] = a0.y;
        As[0][acol + 2][arow] = a0.z;
        As[0][acol + 3][arow] = a0.w;
        As[0][acol + 4][arow] = a1.x;
        As[0][acol + 5][arow] = a1.y;
        As[0][acol + 6][arow] = a1.z;
        As[0][acol + 7][arow] = a1.w;
        float4 b0 = *(const float4*)(Bptr);
        float4 b1 = *(const float4*)(Bptr + 4);
        *(float4*)&Bs[0][brow][bcol]     = b0;
        *(float4*)&Bs[0][brow][bcol + 4] = b1;
    }
    __syncthreads();

    const int NT = DD / BK;   // 8
    int buf = 0;
    for (int kt = 0; kt < NT; kt++) {
        float4 a0 = make_float4(0.f, 0.f, 0.f, 0.f);
        float4 a1 = make_float4(0.f, 0.f, 0.f, 0.f);
        float4 b0, b1;
        bool have_next = (kt + 1 < NT);
        if (have_next) {
            int k0 = (kt + 1) * BK;
            if (arow_ok) {
                a0 = *(const float4*)(Aptr + k0);
                a1 = *(const float4*)(Aptr + k0 + 4);
            }
            b0 = *(const float4*)(Bptr + (size_t)k0 * NCAT);
            b1 = *(const float4*)(Bptr + (size_t)k0 * NCAT + 4);
        }

#pragma unroll
        for (int k = 0; k < BK; k++) {
            float ra[8], rb[8];
#pragma unroll
            for (int i = 0; i < 8; i++) ra[i] = As[buf][k][tr + i];
#pragma unroll
            for (int j = 0; j < 8; j++) rb[j] = Bs[buf][k][tc + j];
#pragma unroll
            for (int i = 0; i < 8; i++)
#pragma unroll
                for (int j = 0; j < 8; j++) acc[i][j] += ra[i] * rb[j];
        }

        if (have_next) {
            int nb = buf ^ 1;
            __syncthreads();
            As[nb][acol + 0][arow] = a0.x;
            As[nb][acol + 1][arow] = a0.y;
            As[nb][acol + 2][arow] = a0.z;
            As[nb][acol + 3][arow] = a0.w;
            As[nb][acol + 4][arow] = a1.x;
            As[nb][acol + 5][arow] = a1.y;
            As[nb][acol + 6][arow] = a1.z;
            As[nb][acol + 7][arow] = a1.w;
            *(float4*)&Bs[nb][brow][bcol]     = b0;
            *(float4*)&Bs[nb][brow][bcol + 4] = b1;
            __syncthreads();
            buf = nb;
        }
    }

    // ---- segment-routed epilogue ----
    if (bx < 3) {
#pragma unroll
        for (int i = 0; i < 8; i++) {
            int r = row0 + tr + i;
            if (r < M) {
#pragma unroll
                for (int j = 0; j < 8; j += 4)
                    *(float4*)(Y384 + (size_t)r * 384 + bx * 128 + tc + j) =
                        make_float4(acc[i][j], acc[i][j+1], acc[i][j+2], acc[i][j+3]);
            }
        }
    } else if (bx == 5) {
#pragma unroll
        for (int i = 0; i < 8; i++) {
            int r = row0 + tr + i;
            if (r < M) {
#pragma unroll
                for (int j = 0; j < 8; j += 4)
                    *(float4*)(h + (size_t)r * DD + tc + j) =
                        make_float4(acc[i][j], acc[i][j+1], acc[i][j+2], acc[i][j+3]);
            }
        }
    } else {
        float* dstb = (bx == 3) ? beta : gamma;
        int boff = (bx == 3) ? 0 : 128;
        float bias[8];
#pragma unroll
        for (int j = 0; j < 8; j++) bias[j] = __ldg(bf + boff + tc + j);
#pragma unroll
        for (int i = 0; i < 8; i++) {
            int r = row0 + tr + i;
            if (r < M) {
#pragma unroll
                for (int j = 0; j < 8; j += 4)
                    *(float4*)(dstb + (size_t)r * DD + tc + j) =
                        make_float4(acc[i][j] + bias[j],     acc[i][j+1] + bias[j+1],
                                    acc[i][j+2] + bias[j+2], acc[i][j+3] + bias[j+3]);
            }
        }
    }
}

// ---------------- aggregation + skip + combine: one warp per dst node -------
// out = relu(gamma_s * xs + beta_s) computed inline from Y384 staging;
// x_out = out + (sum_e relu(gamma*h[src]+beta)) * deg_inv  [+ relu]
// Edge loop is software-pipelined: next group's src indices prefetched while
// gathering current group's h rows (srcs padded by 8 -> unconditional loads).
__global__ __launch_bounds__(256) void agg_combine_kernel(const int* __restrict__ base,
                                                          const int* __restrict__ srcs,
                                                          const float* __restrict__ h,
                                                          const float* __restrict__ gamma,
                                                          const float* __restrict__ beta,
                                                          const float* __restrict__ Y384,
                                                          const float* __restrict__ deginv,
                                                          float* __restrict__ xout,
                                                          int do_relu) {
    int node = (int)((blockIdx.x * blockDim.x + threadIdx.x) >> 5);
    int lane = threadIdx.x & 31;
    if (node >= NN) return;

    // skip-branch inputs from staging (issued early; consumed after the loop)
    const float* yr = Y384 + (size_t)node * 384;
    float4 bs = __ldg((const float4*)(yr)       + lane);
    float4 gs = __ldg((const float4*)(yr + 128) + lane);
    float4 xs = __ldg((const float4*)(yr + 256) + lane);

    const float4 g = __ldg((const float4*)(gamma + (size_t)node * DD) + lane);
    const float4 b = __ldg((const float4*)(beta  + (size_t)node * DD) + lane);

    int e0 = __ldg(base + node);
    int e1 = __ldg(base + node + 1);

    float4 acc = make_float4(0.f, 0.f, 0.f, 0.f);
    int e = e0;

    // prime the index pipeline (safe: srcs has +8 pad beyond EE)
    int p0 = __ldg(srcs + e);
    int p1 = __ldg(srcs + e + 1);
    int p2 = __ldg(srcs + e + 2);
    int p3 = __ldg(srcs + e + 3);

    for (; e + 4 <= e1; e += 4) {
        int s0 = p0, s1 = p1, s2 = p2, s3 = p3;
        // prefetch next group's indices (overlaps the gathers below)
        p0 = __ldg(srcs + e + 4);
        p1 = __ldg(srcs + e + 5);
        p2 = __ldg(srcs + e + 6);
        p3 = __ldg(srcs + e + 7);

        float4 h0 = __ldg((const float4*)(h + (size_t)s0 * DD) + lane);
        float4 h1 = __ldg((const float4*)(h + (size_t)s1 * DD) + lane);
        float4 h2 = __ldg((const float4*)(h + (size_t)s2 * DD) + lane);
        float4 h3 = __ldg((const float4*)(h + (size_t)s3 * DD) + lane);
        acc.x += fmaxf(fmaf(g.x, h0.x, b.x), 0.0f) + fmaxf(fmaf(g.x, h1.x, b.x), 0.0f)
               + fmaxf(fmaf(g.x, h2.x, b.x), 0.0f) + fmaxf(fmaf(g.x, h3.x, b.x), 0.0f);
        acc.y += fmaxf(fmaf(g.y, h0.y, b.y), 0.0f) + fmaxf(fmaf(g.y, h1.y, b.y), 0.0f)
               + fmaxf(fmaf(g.y, h2.y, b.y), 0.0f) + fmaxf(fmaf(g.y, h3.y, b.y), 0.0f);
        acc.z += fmaxf(fmaf(g.z, h0.z, b.z), 0.0f) + fmaxf(fmaf(g.z, h1.z, b.z), 0.0f)
               + fmaxf(fmaf(g.z, h2.z, b.z), 0.0f) + fmaxf(fmaf(g.z, h3.z, b.z), 0.0f);
        acc.w += fmaxf(fmaf(g.w, h0.w, b.w), 0.0f) + fmaxf(fmaf(g.w, h1.w, b.w), 0.0f)
               + fmaxf(fmaf(g.w, h2.w, b.w), 0.0f) + fmaxf(fmaf(g.w, h3.w, b.w), 0.0f);
    }

    // tail: 0..3 edges, indices already in p0..p2 (loaded from srcs[e..e+2])
    int r = e1 - e;
    if (r > 0) {
        float4 h0 = __ldg((const float4*)(h + (size_t)p0 * DD) + lane);
        acc.x += fmaxf(fmaf(g.x, h0.x, b.x), 0.0f);
        acc.y += fmaxf(fmaf(g.y, h0.y, b.y), 0.0f);
        acc.z += fmaxf(fmaf(g.z, h0.z, b.z), 0.0f);
        acc.w += fmaxf(fmaf(g.w, h0.w, b.w), 0.0f);
    }
    if (r > 1) {
        float4 h1 = __ldg((const float4*)(h + (size_t)p1 * DD) + lane);
        acc.x += fmaxf(fmaf(g.x, h1.x, b.x), 0.0f);
        acc.y += fmaxf(fmaf(g.y, h1.y, b.y), 0.0f);
        acc.z += fmaxf(fmaf(g.z, h1.z, b.z), 0.0f);
        acc.w += fmaxf(fmaf(g.w, h1.w, b.w), 0.0f);
    }
    if (r > 2) {
        float4 h2 = __ldg((const float4*)(h + (size_t)p2 * DD) + lane);
        acc.x += fmaxf(fmaf(g.x, h2.x, b.x), 0.0f);
        acc.y += fmaxf(fmaf(g.y, h2.y, b.y), 0.0f);
        acc.z += fmaxf(fmaf(g.z, h2.z, b.z), 0.0f);
        acc.w += fmaxf(fmaf(g.w, h2.w, b.w), 0.0f);
    }

    float di = __ldg(deginv + node);
    float4 o;
    o.x = fmaxf(fmaf(gs.x, xs.x, bs.x), 0.0f);
    o.y = fmaxf(fmaf(gs.y, xs.y, bs.y), 0.0f);
    o.z = fmaxf(fmaf(gs.z, xs.z, bs.z), 0.0f);
    o.w = fmaxf(fmaf(gs.w, xs.w, bs.w), 0.0f);

    float4 res;
    res.x = o.x + acc.x * di;
    res.y = o.y + acc.y * di;
    res.z = o.z + acc.z * di;
    res.w = o.w + acc.w * di;
    if (do_relu) {
        res.x = fmaxf(res.x, 0.f); res.y = fmaxf(res.y, 0.f);
        res.z = fmaxf(res.z, 0.f); res.w = fmaxf(res.w, 0.f);
    }
    *((float4*)(xout + (size_t)node * DD) + lane) = res;
}

// ---------------- launch ----------------------------------------------------
extern "C" void kernel_launch(void* const* d_in, const int* in_sizes, int n_in,
                              void* d_out, int out_size) {
    const float* x       = (const float*)d_in[0];
    const void*  eidx    = d_in[1];                 // int32 or int64; detected on device
    const float* W_lin   = (const float*)d_in[2];
    const float* W_film  = (const float*)d_in[3];
    const float* b_film  = (const float*)d_in[4];
    const float* W_skip  = (const float*)d_in[5];
    const float* W_fskip = (const float*)d_in[6];
    float*       outp    = (float*)d_out;

    float *Wcat, *Y, *ga, *be, *h, *xb0, *xb1, *deginv;
    int *counts, *base, *cursor, *srcs, *is64;
    cudaGetSymbolAddress((void**)&Wcat,   g_Wcat);
    cudaGetSymbolAddress((void**)&Y,      g_Y);
    cudaGetSymbolAddress((void**)&ga,     g_gamma);
    cudaGetSymbolAddress((void**)&be,     g_beta);
    cudaGetSymbolAddress((void**)&h,      g_h);
    cudaGetSymbolAddress((void**)&xb0,    g_xb0);
    cudaGetSymbolAddress((void**)&xb1,    g_xb1);
    cudaGetSymbolAddress((void**)&deginv, g_deginv);
    cudaGetSymbolAddress((void**)&counts, g_counts);
    cudaGetSymbolAddress((void**)&base,   g_base);
    cudaGetSymbolAddress((void**)&cursor, g_cursor);
    cudaGetSymbolAddress((void**)&srcs,   g_srcs);
    cudaGetSymbolAddress((void**)&is64,   g_is64);

    // dtype probe + pack weights
    detect_kernel<<<1, 1>>>(eidx, is64);
    {
        int tot = NLAYERS * DD * NCAT;
        pack_weights_kernel<<<(tot + 255) / 256, 256>>>(W_lin, W_film, W_skip, W_fskip, Wcat);
    }

    // CSR build (by dst)
    zero_int_kernel<<<(NN + 255) / 256, 256>>>(counts, NN);
    count_kernel<<<(EE + 255) / 256, 256>>>(eidx, is64, counts);
    scan_kernel<<<1, 1024>>>(counts, base, cursor, deginv);
    scatter_kernel<<<(EE + 255) / 256, 256>>>(eidx, is64, cursor, srcs);

    const int nodeWarpBlocks = (NN * 32 + 255) / 256;
    dim3 gemmGrid(6, (NN + 127) / 128);

    const float* xin = x;
    for (int l = 0; l < NLAYERS; l++) {
        sgemm_kernel<<<gemmGrid, 256>>>(xin, Wcat + (size_t)l * DD * NCAT,
                                        b_film + (size_t)l * 256, Y, be, ga, h, NN);

        float* xout;
        if (l == NLAYERS - 1)      xout = outp;
        else if ((l & 1) == 0)     xout = xb0;
        else                       xout = xb1;

        agg_combine_kernel<<<nodeWarpBlocks, 256>>>(base, srcs, h, ga, be, Y, deginv,
                                                    xout, (l < NLAYERS - 1) ? 1 : 0);
        xin = xout;
    }
}